// round 8
// baseline (speedup 1.0000x reference)
#include <cuda_runtime.h>

#define NN 50000
#define NE 800000

// ---------------- scratch (device globals; no allocations) ----------------
__device__ int   g_is64;
__device__ int   g_cnt[NN];
__device__ int   g_cursor[NN];
__device__ int   g_ptr[NN + 1];
__device__ __align__(16) float g_invdeg[NN];
__device__ int   g_csr_src[NE];

__device__ __align__(16) float g_A1 [(size_t)NN * 128];   // [mean(x) | x]
__device__ __align__(16) float g_h1 [(size_t)NN * 256];
__device__ __align__(16) float g_pre[(size_t)NN * 256];   // [t | r] for layers 2/3
__device__ __align__(16) float g_m  [(size_t)NN * 128];   // aggregated t
__device__ __align__(16) float g_h2 [(size_t)NN * 128];
__device__ __align__(16) float g_h3 [(size_t)NN * 128];
__device__ __align__(16) float g_Wf [128 * 256];          // [Wf_l ; Wf_r] row-concat
__device__ __align__(16) float g_W0 [256 * 256];          // [W0_l | W0_r] col-concat
__device__ __align__(16) float g_W1 [128 * 256];          // [W1_l | W1_r] col-concat
__device__ __align__(16) float g_Wc [128 * 8];            // W_lin @ W_lin2
__device__ __align__(16) float g_bc [8];                  // b_lin @ W_lin2 + b_lin2

// ---------------- edge-index dtype detection (int32 vs int64) ----------------
// If dtype is int64 with values < NN, every high 32-bit word is 0.
// If dtype is int32, "high words" are actually node ids (random in [0,NN)).
__global__ void detect_kernel(const unsigned int* __restrict__ w) {
    int is64 = 1;
    for (int i = 0; i < 256; i++) {
        if (w[2 * i + 1] != 0u) { is64 = 0; break; }
    }
    g_is64 = is64;
}

__device__ __forceinline__ int load_idx(const void* ei, long long pos) {
    if (g_is64) return (int)((const long long*)ei)[pos];
    return ((const int*)ei)[pos];
}

// ---------------- CSR build ----------------
__global__ void zero_kernel() {
    int i = blockIdx.x * blockDim.x + threadIdx.x;
    if (i < NN) { g_cnt[i] = 0; g_cursor[i] = 0; }
}

__global__ void deg_kernel(const void* __restrict__ ei) {
    int e = blockIdx.x * blockDim.x + threadIdx.x;
    if (e >= NE) return;
    int t = load_idx(ei, (long long)NE + e);
    if ((unsigned)t < NN) atomicAdd(&g_cnt[t], 1);
}

__global__ void scan_kernel() {
    __shared__ int sh[1024];
    __shared__ int carry;
    int tid = threadIdx.x;
    if (tid == 0) carry = 0;
    __syncthreads();
    for (int base = 0; base < NN; base += 1024) {
        int i = base + tid;
        int v = (i < NN) ? g_cnt[i] : 0;
        sh[tid] = v;
        __syncthreads();
        for (int off = 1; off < 1024; off <<= 1) {
            int add = (tid >= off) ? sh[tid - off] : 0;
            __syncthreads();
            sh[tid] += add;
            __syncthreads();
        }
        if (i < NN) {
            g_ptr[i] = carry + sh[tid] - v;       // exclusive
            g_invdeg[i] = 1.0f / fmaxf((float)v, 1.0f);
        }
        __syncthreads();
        if (tid == 1023) carry += sh[1023];
        __syncthreads();
    }
    if (threadIdx.x == 0) g_ptr[NN] = carry;
}

__global__ void fill_kernel(const void* __restrict__ ei) {
    int e = blockIdx.x * blockDim.x + threadIdx.x;
    if (e >= NE) return;
    int t = load_idx(ei, (long long)NE + e);
    int s = load_idx(ei, e);
    if ((unsigned)t >= NN || (unsigned)s >= NN) return;
    int pos = g_ptr[t] + atomicAdd(&g_cursor[t], 1);
    if ((unsigned)pos < NE) g_csr_src[pos] = s;
}

// ---------------- mean aggregation (gather-side) ----------------
// SRC: 0 = external pointer (x, ld=64), 1 = g_pre (first 128 of 256-wide rows)
// DST: 0 = g_A1 (left half, ldo=128), 1 = g_m (ldo=128)
template <int D, int SRC, int DST>
__global__ void agg_kernel(const float* __restrict__ feat_ext) {
    constexpr int G = D / 4;
    const float* feat = (SRC == 0) ? feat_ext : g_pre;
    const int ld  = (SRC == 0) ? 64 : 256;
    float* out    = (DST == 0) ? g_A1 : g_m;
    const int ldo = 128;
    int gid  = (blockIdx.x * blockDim.x + threadIdx.x) / G;
    int lane = threadIdx.x % G;
    if (gid >= NN) return;
    int beg = g_ptr[gid];
    int cnt = g_cnt[gid];
    float4 acc = make_float4(0.f, 0.f, 0.f, 0.f);
    for (int e = 0; e < cnt; e++) {
        int s = __ldg(&g_csr_src[beg + e]);
        float4 v = __ldg((const float4*)(feat + (size_t)s * ld) + lane);
        acc.x += v.x; acc.y += v.y; acc.z += v.z; acc.w += v.w;
    }
    float inv = g_invdeg[gid];
    acc.x *= inv; acc.y *= inv; acc.z *= inv; acc.w *= inv;
    *((float4*)(out + (size_t)gid * ldo) + lane) = acc;
}

// ---------------- weight staging ----------------
// Wf = [Wf_l ; Wf_r] row-concat (each 64x256)
__global__ void stage_wf_kernel(const float4* __restrict__ wl, const float4* __restrict__ wr) {
    int i = blockIdx.x * blockDim.x + threadIdx.x;  // 0 .. 2*4096-1 (float4)
    int n4 = 64 * 256 / 4;
    if (i < n4) ((float4*)g_Wf)[i] = wl[i];
    else if (i < 2 * n4) ((float4*)g_Wf)[i] = wr[i - n4];
}

// col-concat into g_W0 or g_W1: dst[K][256] = [a | b], halves 128 wide (32 float4)
template <int WSEL>
__global__ void colcat_kernel(const float4* __restrict__ a, const float4* __restrict__ b, int K) {
    float4* dst = (WSEL == 0) ? (float4*)g_W0 : (float4*)g_W1;
    int idx = blockIdx.x * blockDim.x + threadIdx.x;
    if (idx >= K * 64) return;
    int k = idx / 64;
    int j = idx % 64;
    dst[idx] = (j < 32) ? a[k * 32 + j] : b[k * 32 + j - 32];
}

// pack x into right half of A1 (cols 64..127)
__global__ void pack_x_kernel(const float4* __restrict__ x4) {
    int idx = blockIdx.x * blockDim.x + threadIdx.x;
    if (idx >= NN * 16) return;
    int i = idx >> 4, j = idx & 15;
    ((float4*)g_A1)[i * 32 + 16 + j] = x4[idx];
}

// h = relu(m + bias + pre[:,128:256]); HSEL: 0 -> g_h2, 1 -> g_h3
template <int HSEL>
__global__ void ew_kernel(const float* __restrict__ bias) {
    float* h = (HSEL == 0) ? g_h2 : g_h3;
    int idx = blockIdx.x * blockDim.x + threadIdx.x;   // float4 index over N*32
    if (idx >= NN * 32) return;
    int i = idx >> 5, j = idx & 31;
    float4 mv = ((const float4*)g_m)[idx];
    float4 pv = ((const float4*)g_pre)[i * 64 + 32 + j];
    float4 bv = ((const float4*)bias)[j];
    float4 r;
    r.x = fmaxf(mv.x + pv.x + bv.x, 0.f);
    r.y = fmaxf(mv.y + pv.y + bv.y, 0.f);
    r.z = fmaxf(mv.z + pv.z + bv.z, 0.f);
    r.w = fmaxf(mv.w + pv.w + bv.w, 0.f);
    ((float4*)h)[idx] = r;
}

// ---------------- SGEMM: C[M,256] = A[M,K] @ B[K,256] (+bias)(+relu) ----------------
// ASEL: 0=g_A1(K=128), 1=g_h1(K=256), 2=g_h2(K=128)
// BSEL: 0=g_Wf, 1=g_W0, 2=g_W1
// CSEL: 0=g_h1, 1=g_pre
template <int ASEL, int BSEL, int CSEL, bool BIAS, bool RELU>
__global__ __launch_bounds__(256, 2)
void sgemm_kernel(const float* __restrict__ bias) {
    const float* A = (ASEL == 0) ? g_A1 : (ASEL == 1) ? g_h1 : g_h2;
    const int K    = (ASEL == 1) ? 256 : 128;
    const float* B = (BSEL == 0) ? g_Wf : (BSEL == 1) ? g_W0 : g_W1;
    float* C       = (CSEL == 0) ? g_h1 : g_pre;
    const int Nc = 256;
    const int M  = NN;

    __shared__ __align__(16) float As[8][128];
    __shared__ __align__(16) float Bs[8][128];
    int tid  = threadIdx.x;
    int brow = blockIdx.x * 128;
    int bcol = blockIdx.y * 128;
    int tr = (tid / 16) * 8;
    int tc = (tid % 16) * 8;
    float acc[8][8];
#pragma unroll
    for (int i = 0; i < 8; i++)
#pragma unroll
        for (int j = 0; j < 8; j++) acc[i][j] = 0.f;

    int arow = tid >> 1;            // 0..127
    int ak   = (tid & 1) * 4;       // 0 or 4
    int bk   = tid >> 5;            // 0..7
    int bc4  = (tid & 31) * 4;      // 0..124

    for (int k0 = 0; k0 < K; k0 += 8) {
        int gr = brow + arow;
        float4 av = make_float4(0.f, 0.f, 0.f, 0.f);
        if (gr < M) av = *(const float4*)(A + (size_t)gr * K + k0 + ak);
        As[ak + 0][arow] = av.x;
        As[ak + 1][arow] = av.y;
        As[ak + 2][arow] = av.z;
        As[ak + 3][arow] = av.w;
        float4 bv = *(const float4*)(B + (size_t)(k0 + bk) * Nc + bcol + bc4);
        *(float4*)&Bs[bk][bc4] = bv;
        __syncthreads();
#pragma unroll
        for (int k = 0; k < 8; k++) {
            float4 a0 = *(const float4*)&As[k][tr];
            float4 a1 = *(const float4*)&As[k][tr + 4];
            float4 b0 = *(const float4*)&Bs[k][tc];
            float4 b1 = *(const float4*)&Bs[k][tc + 4];
            float ra[8] = {a0.x, a0.y, a0.z, a0.w, a1.x, a1.y, a1.z, a1.w};
            float rb[8] = {b0.x, b0.y, b0.z, b0.w, b1.x, b1.y, b1.z, b1.w};
#pragma unroll
            for (int i = 0; i < 8; i++)
#pragma unroll
                for (int j = 0; j < 8; j++) acc[i][j] += ra[i] * rb[j];
        }
        __syncthreads();
    }
    // epilogue
#pragma unroll
    for (int i = 0; i < 8; i++) {
        int gr = brow + tr + i;
        if (gr >= M) break;
#pragma unroll
        for (int j = 0; j < 8; j += 4) {
            float4 v = make_float4(acc[i][j], acc[i][j + 1], acc[i][j + 2], acc[i][j + 3]);
            if (BIAS) {
                float4 bvv = *(const float4*)(bias + bcol + tc + j);
                v.x += bvv.x; v.y += bvv.y; v.z += bvv.z; v.w += bvv.w;
            }
            if (RELU) {
                v.x = fmaxf(v.x, 0.f); v.y = fmaxf(v.y, 0.f);
                v.z = fmaxf(v.z, 0.f); v.w = fmaxf(v.w, 0.f);
            }
            *(float4*)(C + (size_t)gr * Nc + bcol + tc + j) = v;
        }
    }
}

// ---------------- head: fold two linears into one ----------------
__global__ void combine_head_kernel(const float* __restrict__ Wlin, const float* __restrict__ blin,
                                    const float* __restrict__ Wlin2, const float* __restrict__ blin2) {
    int i = threadIdx.x;   // 128 threads
    float acc[8];
#pragma unroll
    for (int j = 0; j < 8; j++) acc[j] = 0.f;
    for (int k = 0; k < 128; k++) {
        float a = Wlin[i * 128 + k];
#pragma unroll
        for (int j = 0; j < 8; j++) acc[j] += a * Wlin2[k * 8 + j];
    }
#pragma unroll
    for (int j = 0; j < 8; j++) g_Wc[i * 8 + j] = acc[j];
    if (i < 8) {
        float s = blin2[i];
        for (int k = 0; k < 128; k++) s += blin[k] * Wlin2[k * 8 + i];
        g_bc[i] = s;
    }
}

// out[N,8] = h3 @ Wc + bc ; one warp per row
__global__ void head_kernel(float* __restrict__ out) {
    __shared__ float sW[8][128];
    __shared__ float sb[8];
    int tid = threadIdx.x;
    for (int i = tid; i < 1024; i += blockDim.x) {
        int k = i >> 3, j = i & 7;
        sW[j][k] = g_Wc[k * 8 + j];
    }
    if (tid < 8) sb[tid] = g_bc[tid];
    __syncthreads();
    int warp = tid / 32, lane = tid % 32;
    int row = blockIdx.x * 8 + warp;
    if (row >= NN) return;
    float4 a = *(const float4*)(g_h3 + (size_t)row * 128 + lane * 4);
    float acc[8];
#pragma unroll
    for (int j = 0; j < 8; j++) {
        float4 w = *(const float4*)&sW[j][lane * 4];
        acc[j] = a.x * w.x + a.y * w.y + a.z * w.z + a.w * w.w;
    }
#pragma unroll
    for (int j = 0; j < 8; j++) {
        float v = acc[j];
#pragma unroll
        for (int off = 16; off; off >>= 1) v += __shfl_down_sync(0xFFFFFFFFu, v, off);
        if (lane == 0) out[row * 8 + j] = v + sb[j];
    }
}

// ---------------- launch ----------------
extern "C" void kernel_launch(void* const* d_in, const int* in_sizes, int n_in,
                              void* d_out, int out_size) {
    const float* x      = (const float*)d_in[0];
    const void*  ei     = d_in[1];
    const float* Wf_l   = (const float*)d_in[2];
    const float* bf     = (const float*)d_in[3];
    const float* Wf_r   = (const float*)d_in[4];
    const float* W0_l   = (const float*)d_in[5];
    const float* b0     = (const float*)d_in[6];
    const float* W0_r   = (const float*)d_in[7];
    const float* W1_l   = (const float*)d_in[8];
    const float* b1     = (const float*)d_in[9];
    const float* W1_r   = (const float*)d_in[10];
    const float* W_lin  = (const float*)d_in[11];
    const float* b_lin  = (const float*)d_in[12];
    const float* W_lin2 = (const float*)d_in[13];
    const float* b_lin2 = (const float*)d_in[14];
    float* out = (float*)d_out;

    const int TB = 256;
    // ---- dtype probe + CSR build ----
    detect_kernel<<<1, 1>>>((const unsigned int*)ei);
    zero_kernel<<<(NN + TB - 1) / TB, TB>>>();
    deg_kernel<<<(NE + TB - 1) / TB, TB>>>(ei);
    scan_kernel<<<1, 1024>>>();
    fill_kernel<<<(NE + TB - 1) / TB, TB>>>(ei);

    // ---- weight staging (independent of CSR) ----
    stage_wf_kernel<<<(2 * 64 * 64 + TB - 1) / TB, TB>>>((const float4*)Wf_l, (const float4*)Wf_r);
    colcat_kernel<0><<<(256 * 64 + TB - 1) / TB, TB>>>((const float4*)W0_l, (const float4*)W0_r, 256);
    colcat_kernel<1><<<(128 * 64 + TB - 1) / TB, TB>>>((const float4*)W1_l, (const float4*)W1_r, 128);
    combine_head_kernel<<<1, 128>>>(W_lin, b_lin, W_lin2, b_lin2);
    pack_x_kernel<<<(NN * 16 + TB - 1) / TB, TB>>>((const float4*)x);

    // ---- layer 1: A1 = [mean(x) | x];  h1 = relu(A1 @ Wf + bf) ----
    agg_kernel<64, 0, 0><<<(NN * 16 + TB - 1) / TB, TB>>>(x);
    {
        dim3 grid((NN + 127) / 128, 2);
        sgemm_kernel<0, 0, 0, true, true><<<grid, 256>>>(bf);
    }
    // ---- layer 2: pre = h1 @ [W0_l|W0_r]; m = mean(pre[:,:128]); h2 = relu(m+b0+pre[:,128:]) ----
    {
        dim3 grid((NN + 127) / 128, 2);
        sgemm_kernel<1, 1, 1, false, false><<<grid, 256>>>(nullptr);
    }
    agg_kernel<128, 1, 1><<<(NN * 32 + TB - 1) / TB, TB>>>(nullptr);
    ew_kernel<0><<<(NN * 32 + TB - 1) / TB, TB>>>(b0);

    // ---- layer 3 ----
    {
        dim3 grid((NN + 127) / 128, 2);
        sgemm_kernel<2, 2, 1, false, false><<<grid, 256>>>(nullptr);
    }
    agg_kernel<128, 1, 1><<<(NN * 32 + TB - 1) / TB, TB>>>(nullptr);
    ew_kernel<1><<<(NN * 32 + TB - 1) / TB, TB>>>(b1);

    // ---- folded head ----
    head_kernel<<<(NN + 7) / 8, 256>>>(out);
    (void)in_sizes; (void)n_in; (void)out_size;
}

// round 10
// speedup vs baseline: 1.1901x; 1.1901x over previous
#include <cuda_runtime.h>

#define NN 50000
#define NE 800000
#define NB ((NN + 1023) / 1024)

typedef unsigned long long u64;

// ---------------- scratch (device globals; no allocations) ----------------
__device__ int   g_is64;
__device__ int   g_cnt[NN];
__device__ int   g_cursor[NN];
__device__ int   g_ptr[NN + 1];
__device__ int   g_bsum[64];
__device__ int   g_boff[64];
__device__ __align__(16) float g_invdeg[NN];
__device__ int   g_csr_src[NE];

__device__ __align__(16) float g_A1 [(size_t)NN * 128];   // [mean(x) | x]
__device__ __align__(16) float g_h1 [(size_t)NN * 256];
__device__ __align__(16) float g_pre[(size_t)NN * 256];   // [t | r] for layers 2/3
__device__ __align__(16) float g_h2 [(size_t)NN * 128];
__device__ __align__(16) float g_h3 [(size_t)NN * 128];
__device__ __align__(16) float g_Wf [128 * 256];          // [Wf_l ; Wf_r] row-concat
__device__ __align__(16) float g_W0 [256 * 256];          // [W0_l | W0_r] col-concat
__device__ __align__(16) float g_W1 [128 * 256];          // [W1_l | W1_r] col-concat
__device__ __align__(16) float g_Wc [128 * 8];            // W_lin @ W_lin2
__device__ __align__(16) float g_bc [8];                  // b_lin @ W_lin2 + b_lin2

// ---------------- packed fp32x2 helpers ----------------
__device__ __forceinline__ void ffma2(u64& d, u64 a, u64 b) {
    asm("fma.rn.f32x2 %0, %1, %2, %0;" : "+l"(d) : "l"(a), "l"(b));
}
__device__ __forceinline__ u64 dup2(float a) {
    u64 r;
    unsigned int ai = __float_as_uint(a);
    asm("mov.b64 %0, {%1, %1};" : "=l"(r) : "r"(ai));
    return r;
}
union F4U { float4 f; u64 u[2]; };

// ---------------- edge-index dtype detection (int32 vs int64) ----------------
__global__ void detect_kernel(const unsigned int* __restrict__ w) {
    __shared__ int flag;
    int tid = threadIdx.x;
    if (tid == 0) flag = 0;
    __syncthreads();
    if (w[2 * tid + 1] != 0u) flag = 1;   // high word of putative int64
    __syncthreads();
    if (tid == 0) g_is64 = !flag;
}

__device__ __forceinline__ int load_idx(const void* ei, long long pos) {
    if (g_is64) return (int)((const long long*)ei)[pos];
    return ((const int*)ei)[pos];
}

// ---------------- CSR build ----------------
__global__ void zero_kernel() {
    int i = blockIdx.x * blockDim.x + threadIdx.x;
    if (i < NN) { g_cnt[i] = 0; g_cursor[i] = 0; }
}

__global__ void deg_kernel(const void* __restrict__ ei) {
    int e = blockIdx.x * blockDim.x + threadIdx.x;
    if (e >= NE) return;
    int t = load_idx(ei, (long long)NE + e);
    if ((unsigned)t < NN) atomicAdd(&g_cnt[t], 1);
}

// ---- 3-phase scan ----
__global__ void scanA_kernel() {
    int tid = threadIdx.x, lane = tid & 31, warp = tid >> 5;
    int i = blockIdx.x * 1024 + tid;
    int v = (i < NN) ? g_cnt[i] : 0;
    int x = v;
#pragma unroll
    for (int off = 1; off < 32; off <<= 1) {
        int n = __shfl_up_sync(0xFFFFFFFFu, x, off);
        if (lane >= off) x += n;
    }
    __shared__ int ws[32];
    if (lane == 31) ws[warp] = x;
    __syncthreads();
    if (warp == 0) {
        int s = ws[lane];
#pragma unroll
        for (int off = 1; off < 32; off <<= 1) {
            int n = __shfl_up_sync(0xFFFFFFFFu, s, off);
            if (lane >= off) s += n;
        }
        ws[lane] = s;
    }
    __syncthreads();
    int base = warp ? ws[warp - 1] : 0;
    int incl = x + base;
    if (i < NN) {
        g_ptr[i] = incl - v;                       // block-local exclusive
        g_invdeg[i] = 1.0f / fmaxf((float)v, 1.0f);
    }
    if (tid == 1023) g_bsum[blockIdx.x] = incl;    // block total
}

__global__ void scanB_kernel() {   // 1 block, 64 threads
    int tid = threadIdx.x, lane = tid & 31, warp = tid >> 5;
    int v = (tid < NB) ? g_bsum[tid] : 0;
    int x = v;
#pragma unroll
    for (int off = 1; off < 32; off <<= 1) {
        int n = __shfl_up_sync(0xFFFFFFFFu, x, off);
        if (lane >= off) x += n;
    }
    __shared__ int ws[2];
    if (lane == 31) ws[warp] = x;
    __syncthreads();
    int base = warp ? ws[0] : 0;
    int incl = x + base;
    if (tid < NB) g_boff[tid] = incl - v;
    if (tid == NB - 1) g_ptr[NN] = incl;
}

__global__ void scanC_kernel() {
    int i = blockIdx.x * 1024 + threadIdx.x;
    if (i < NN) g_ptr[i] += g_boff[blockIdx.x];
}

__global__ void fill_kernel(const void* __restrict__ ei) {
    int e = blockIdx.x * blockDim.x + threadIdx.x;
    if (e >= NE) return;
    int t = load_idx(ei, (long long)NE + e);
    int s = load_idx(ei, e);
    if ((unsigned)t >= NN || (unsigned)s >= NN) return;
    int pos = g_ptr[t] + atomicAdd(&g_cursor[t], 1);
    if ((unsigned)pos < NE) g_csr_src[pos] = s;
}

// ---------------- layer-1 aggregation: mean(x) -> left half of A1 ----------------
__global__ void agg1_kernel(const float* __restrict__ x) {
    int gid  = (blockIdx.x * blockDim.x + threadIdx.x) / 16;
    int lane = threadIdx.x % 16;
    if (gid >= NN) return;
    int beg = g_ptr[gid];
    int cnt = g_cnt[gid];
    float4 acc = make_float4(0.f, 0.f, 0.f, 0.f);
    for (int e = 0; e < cnt; e++) {
        int s = __ldg(&g_csr_src[beg + e]);
        float4 v = __ldg((const float4*)(x + (size_t)s * 64) + lane);
        acc.x += v.x; acc.y += v.y; acc.z += v.z; acc.w += v.w;
    }
    float inv = g_invdeg[gid];
    acc.x *= inv; acc.y *= inv; acc.z *= inv; acc.w *= inv;
    *((float4*)(g_A1 + (size_t)gid * 128) + lane) = acc;
}

// ---------------- fused agg + epilogue for layers 2/3 ----------------
// h = relu(mean(pre[:, :128]) + bias + pre[:, 128:256])
template <int HSEL>
__global__ void agg_ew_kernel(const float* __restrict__ bias) {
    float* h = (HSEL == 0) ? g_h2 : g_h3;
    int gid  = (blockIdx.x * blockDim.x + threadIdx.x) / 32;
    int lane = threadIdx.x % 32;
    if (gid >= NN) return;
    int beg = g_ptr[gid];
    int cnt = g_cnt[gid];
    float4 acc = make_float4(0.f, 0.f, 0.f, 0.f);
    for (int e = 0; e < cnt; e++) {
        int s = __ldg(&g_csr_src[beg + e]);
        float4 v = __ldg((const float4*)(g_pre + (size_t)s * 256) + lane);
        acc.x += v.x; acc.y += v.y; acc.z += v.z; acc.w += v.w;
    }
    float inv = g_invdeg[gid];
    float4 pv = __ldg((const float4*)g_pre + (size_t)gid * 64 + 32 + lane);
    float4 bv = __ldg((const float4*)bias + lane);
    float4 r;
    r.x = fmaxf(acc.x * inv + pv.x + bv.x, 0.f);
    r.y = fmaxf(acc.y * inv + pv.y + bv.y, 0.f);
    r.z = fmaxf(acc.z * inv + pv.z + bv.z, 0.f);
    r.w = fmaxf(acc.w * inv + pv.w + bv.w, 0.f);
    ((float4*)h)[(size_t)gid * 32 + lane] = r;
}

// ---------------- weight staging ----------------
__global__ void stage_wf_kernel(const float4* __restrict__ wl, const float4* __restrict__ wr) {
    int i = blockIdx.x * blockDim.x + threadIdx.x;
    int n4 = 64 * 256 / 4;
    if (i < n4) ((float4*)g_Wf)[i] = wl[i];
    else if (i < 2 * n4) ((float4*)g_Wf)[i] = wr[i - n4];
}

template <int WSEL>
__global__ void colcat_kernel(const float4* __restrict__ a, const float4* __restrict__ b, int K) {
    float4* dst = (WSEL == 0) ? (float4*)g_W0 : (float4*)g_W1;
    int idx = blockIdx.x * blockDim.x + threadIdx.x;
    if (idx >= K * 64) return;
    int k = idx / 64;
    int j = idx % 64;
    dst[idx] = (j < 32) ? a[k * 32 + j] : b[k * 32 + j - 32];
}

__global__ void pack_x_kernel(const float4* __restrict__ x4) {
    int idx = blockIdx.x * blockDim.x + threadIdx.x;
    if (idx >= NN * 16) return;
    int i = idx >> 4, j = idx & 15;
    ((float4*)g_A1)[i * 32 + 16 + j] = x4[idx];
}

// ---------------- SGEMM with packed f32x2 FMA ----------------
// ASEL: 0=g_A1(K=128), 1=g_h1(K=256), 2=g_h2(K=128)
// BSEL: 0=g_Wf, 1=g_W0, 2=g_W1 ; CSEL: 0=g_h1, 1=g_pre
template <int ASEL, int BSEL, int CSEL, bool BIAS, bool RELU>
__global__ __launch_bounds__(256, 2)
void sgemm_kernel(const float* __restrict__ bias) {
    const float* A = (ASEL == 0) ? g_A1 : (ASEL == 1) ? g_h1 : g_h2;
    const int K    = (ASEL == 1) ? 256 : 128;
    const float* B = (BSEL == 0) ? g_Wf : (BSEL == 1) ? g_W0 : g_W1;
    float* C       = (CSEL == 0) ? g_h1 : g_pre;
    const int Nc = 256;
    const int M  = NN;

    __shared__ __align__(16) float As[8][128];
    __shared__ __align__(16) float Bs[8][128];
    int tid  = threadIdx.x;
    int brow = blockIdx.x * 128;
    int bcol = blockIdx.y * 128;
    int tr = (tid / 16) * 8;
    int tc = (tid % 16) * 8;

    u64 acc2[8][4];   // acc2[i][j] = (C[tr+i][tc+2j], C[tr+i][tc+2j+1])
#pragma unroll
    for (int i = 0; i < 8; i++)
#pragma unroll
        for (int j = 0; j < 4; j++) acc2[i][j] = 0ULL;

    int arow = tid >> 1;            // 0..127
    int ak   = (tid & 1) * 4;       // 0 or 4
    int bk   = tid >> 5;            // 0..7
    int bc4  = (tid & 31) * 4;      // 0..124

    for (int k0 = 0; k0 < K; k0 += 8) {
        int gr = brow + arow;
        float4 av = make_float4(0.f, 0.f, 0.f, 0.f);
        if (gr < M) av = *(const float4*)(A + (size_t)gr * K + k0 + ak);
        As[ak + 0][arow] = av.x;
        As[ak + 1][arow] = av.y;
        As[ak + 2][arow] = av.z;
        As[ak + 3][arow] = av.w;
        float4 bv = *(const float4*)(B + (size_t)(k0 + bk) * Nc + bcol + bc4);
        *(float4*)&Bs[bk][bc4] = bv;
        __syncthreads();
#pragma unroll
        for (int k = 0; k < 8; k++) {
            float4 a0 = *(const float4*)&As[k][tr];
            float4 a1 = *(const float4*)&As[k][tr + 4];
            F4U b0, b1;
            b0.f = *(const float4*)&Bs[k][tc];
            b1.f = *(const float4*)&Bs[k][tc + 4];
            u64 bp[4] = { b0.u[0], b0.u[1], b1.u[0], b1.u[1] };
            float ra[8] = {a0.x, a0.y, a0.z, a0.w, a1.x, a1.y, a1.z, a1.w};
#pragma unroll
            for (int i = 0; i < 8; i++) {
                u64 ad = dup2(ra[i]);
                ffma2(acc2[i][0], ad, bp[0]);
                ffma2(acc2[i][1], ad, bp[1]);
                ffma2(acc2[i][2], ad, bp[2]);
                ffma2(acc2[i][3], ad, bp[3]);
            }
        }
        __syncthreads();
    }
    // epilogue
#pragma unroll
    for (int i = 0; i < 8; i++) {
        int gr = brow + tr + i;
        if (gr >= M) break;
        union { u64 u[4]; float f[8]; } row;
#pragma unroll
        for (int j = 0; j < 4; j++) row.u[j] = acc2[i][j];
#pragma unroll
        for (int j = 0; j < 8; j += 4) {
            float4 v = make_float4(row.f[j], row.f[j + 1], row.f[j + 2], row.f[j + 3]);
            if (BIAS) {
                float4 bvv = *(const float4*)(bias + bcol + tc + j);
                v.x += bvv.x; v.y += bvv.y; v.z += bvv.z; v.w += bvv.w;
            }
            if (RELU) {
                v.x = fmaxf(v.x, 0.f); v.y = fmaxf(v.y, 0.f);
                v.z = fmaxf(v.z, 0.f); v.w = fmaxf(v.w, 0.f);
            }
            *(float4*)(C + (size_t)gr * Nc + bcol + tc + j) = v;
        }
    }
}

// ---------------- head: fold two linears into one ----------------
__global__ void combine_head_kernel(const float* __restrict__ Wlin, const float* __restrict__ blin,
                                    const float* __restrict__ Wlin2, const float* __restrict__ blin2) {
    int i = threadIdx.x;   // 128 threads
    float acc[8];
#pragma unroll
    for (int j = 0; j < 8; j++) acc[j] = 0.f;
    for (int k = 0; k < 128; k++) {
        float a = Wlin[i * 128 + k];
#pragma unroll
        for (int j = 0; j < 8; j++) acc[j] += a * Wlin2[k * 8 + j];
    }
#pragma unroll
    for (int j = 0; j < 8; j++) g_Wc[i * 8 + j] = acc[j];
    if (i < 8) {
        float s = blin2[i];
        for (int k = 0; k < 128; k++) s += blin[k] * Wlin2[k * 8 + i];
        g_bc[i] = s;
    }
}

// out[N,8] = h3 @ Wc + bc ; one warp per row
__global__ void head_kernel(float* __restrict__ out) {
    __shared__ float sW[8][128];
    __shared__ float sb[8];
    int tid = threadIdx.x;
    for (int i = tid; i < 1024; i += blockDim.x) {
        int k = i >> 3, j = i & 7;
        sW[j][k] = g_Wc[k * 8 + j];
    }
    if (tid < 8) sb[tid] = g_bc[tid];
    __syncthreads();
    int warp = tid / 32, lane = tid % 32;
    int row = blockIdx.x * 8 + warp;
    if (row >= NN) return;
    float4 a = *(const float4*)(g_h3 + (size_t)row * 128 + lane * 4);
    float acc[8];
#pragma unroll
    for (int j = 0; j < 8; j++) {
        float4 w = *(const float4*)&sW[j][lane * 4];
        acc[j] = a.x * w.x + a.y * w.y + a.z * w.z + a.w * w.w;
    }
#pragma unroll
    for (int j = 0; j < 8; j++) {
        float v = acc[j];
#pragma unroll
        for (int off = 16; off; off >>= 1) v += __shfl_down_sync(0xFFFFFFFFu, v, off);
        if (lane == 0) out[row * 8 + j] = v + sb[j];
    }
}

// ---------------- launch ----------------
extern "C" void kernel_launch(void* const* d_in, const int* in_sizes, int n_in,
                              void* d_out, int out_size) {
    const float* x      = (const float*)d_in[0];
    const void*  ei     = d_in[1];
    const float* Wf_l   = (const float*)d_in[2];
    const float* bf     = (const float*)d_in[3];
    const float* Wf_r   = (const float*)d_in[4];
    const float* W0_l   = (const float*)d_in[5];
    const float* b0     = (const float*)d_in[6];
    const float* W0_r   = (const float*)d_in[7];
    const float* W1_l   = (const float*)d_in[8];
    const float* b1     = (const float*)d_in[9];
    const float* W1_r   = (const float*)d_in[10];
    const float* W_lin  = (const float*)d_in[11];
    const float* b_lin  = (const float*)d_in[12];
    const float* W_lin2 = (const float*)d_in[13];
    const float* b_lin2 = (const float*)d_in[14];
    float* out = (float*)d_out;

    const int TB = 256;
    // ---- dtype probe + CSR build ----
    detect_kernel<<<1, 256>>>((const unsigned int*)ei);
    zero_kernel<<<(NN + TB - 1) / TB, TB>>>();
    deg_kernel<<<(NE + TB - 1) / TB, TB>>>(ei);
    scanA_kernel<<<NB, 1024>>>();
    scanB_kernel<<<1, 64>>>();
    scanC_kernel<<<NB, 1024>>>();
    fill_kernel<<<(NE + TB - 1) / TB, TB>>>(ei);

    // ---- weight staging ----
    stage_wf_kernel<<<(2 * 64 * 64 + TB - 1) / TB, TB>>>((const float4*)Wf_l, (const float4*)Wf_r);
    colcat_kernel<0><<<(256 * 64 + TB - 1) / TB, TB>>>((const float4*)W0_l, (const float4*)W0_r, 256);
    colcat_kernel<1><<<(128 * 64 + TB - 1) / TB, TB>>>((const float4*)W1_l, (const float4*)W1_r, 128);
    combine_head_kernel<<<1, 128>>>(W_lin, b_lin, W_lin2, b_lin2);
    pack_x_kernel<<<(NN * 16 + TB - 1) / TB, TB>>>((const float4*)x);

    // ---- layer 1: A1 = [mean(x) | x];  h1 = relu(A1 @ Wf + bf) ----
    agg1_kernel<<<(NN * 16 + TB - 1) / TB, TB>>>(x);
    {
        dim3 grid((NN + 127) / 128, 2);
        sgemm_kernel<0, 0, 0, true, true><<<grid, 256>>>(bf);
    }
    // ---- layer 2 ----
    {
        dim3 grid((NN + 127) / 128, 2);
        sgemm_kernel<1, 1, 1, false, false><<<grid, 256>>>(nullptr);
    }
    agg_ew_kernel<0><<<(NN * 32 + TB - 1) / TB, TB>>>(b0);

    // ---- layer 3 ----
    {
        dim3 grid((NN + 127) / 128, 2);
        sgemm_kernel<2, 2, 1, false, false><<<grid, 256>>>(nullptr);
    }
    agg_ew_kernel<1><<<(NN * 32 + TB - 1) / TB, TB>>>(b1);

    // ---- folded head ----
    head_kernel<<<(NN + 7) / 8, 256>>>(out);
    (void)in_sizes; (void)n_in; (void)out_size;
}

// round 16
// speedup vs baseline: 2.0019x; 1.6821x over previous
#include <cuda_runtime.h>
#include <cuda_bf16.h>
#include <cstdint>

#define NN 50000
#define NE 800000
#define NB ((NN + 1023) / 1024)

// ---------------- scratch (device globals; no allocations) ----------------
__device__ int   g_is64;
__device__ int   g_cnt[NN];
__device__ int   g_cursor[NN];
__device__ int   g_ptr[NN + 1];
__device__ int   g_bsum[64];
__device__ int   g_boff[64];
__device__ __align__(16) float g_invdeg[NN];
__device__ int   g_csr_src[NE];

__device__ __align__(16) float g_A1 [(size_t)NN * 128];   // [mean(x) | x]
__device__ __align__(16) float g_h1 [(size_t)NN * 256];
__device__ __align__(16) float g_pre[(size_t)NN * 256];   // [t | r] for layers 2/3
__device__ __align__(16) float g_h2 [(size_t)NN * 128];
__device__ __align__(16) float g_h3 [(size_t)NN * 128];
__device__ __align__(16) float g_Wc [128 * 8];            // W_lin @ W_lin2
__device__ __align__(16) float g_bc [8];                  // b_lin @ W_lin2 + b_lin2

// bf16 hi/lo B operands, plain row-major [K][256] per layer.
// Element offsets: L0 @ 0 (128*256), L1 @ 32768 (256*256), L2 @ 98304 (128*256).
__device__ __align__(16) __nv_bfloat16 g_Bh[131072];
__device__ __align__(16) __nv_bfloat16 g_Bl[131072];

// ---------------- helpers ----------------
__device__ __forceinline__ uint32_t smem_u32(const void* p) {
    uint32_t a;
    asm("{ .reg .u64 t; cvta.to.shared.u64 t, %1; cvt.u32.u64 %0, t; }" : "=r"(a) : "l"(p));
    return a;
}
__device__ __forceinline__ void ldmatrix_x4(uint32_t& r0, uint32_t& r1, uint32_t& r2, uint32_t& r3, uint32_t addr) {
    asm volatile("ldmatrix.sync.aligned.m8n8.x4.shared.b16 {%0,%1,%2,%3}, [%4];"
                 : "=r"(r0), "=r"(r1), "=r"(r2), "=r"(r3) : "r"(addr));
}
__device__ __forceinline__ void ldmatrix_x4_trans(uint32_t& r0, uint32_t& r1, uint32_t& r2, uint32_t& r3, uint32_t addr) {
    asm volatile("ldmatrix.sync.aligned.m8n8.x4.trans.shared.b16 {%0,%1,%2,%3}, [%4];"
                 : "=r"(r0), "=r"(r1), "=r"(r2), "=r"(r3) : "r"(addr));
}
__device__ __forceinline__ void mma_bf16(float* d, const uint32_t* a, uint32_t b0, uint32_t b1) {
    asm volatile(
        "mma.sync.aligned.m16n8k16.row.col.f32.bf16.bf16.f32 "
        "{%0,%1,%2,%3}, {%4,%5,%6,%7}, {%8,%9}, {%0,%1,%2,%3};"
        : "+f"(d[0]), "+f"(d[1]), "+f"(d[2]), "+f"(d[3])
        : "r"(a[0]), "r"(a[1]), "r"(a[2]), "r"(a[3]), "r"(b0), "r"(b1));
}
__device__ __forceinline__ void split_bf16(float f, unsigned short& h, unsigned short& l) {
    __nv_bfloat16 hb = __float2bfloat16(f);
    float hf = __bfloat162float(hb);
    __nv_bfloat16 lb = __float2bfloat16(f - hf);
    h = *(unsigned short*)&hb;
    l = *(unsigned short*)&lb;
}

// ---------------- edge-index dtype detection (int32 vs int64) ----------------
__global__ void detect_kernel(const unsigned int* __restrict__ w) {
    __shared__ int flag;
    int tid = threadIdx.x;
    if (tid == 0) flag = 0;
    __syncthreads();
    if (w[2 * tid + 1] != 0u) flag = 1;
    __syncthreads();
    if (tid == 0) g_is64 = !flag;
}

__device__ __forceinline__ int load_idx(const void* ei, long long pos) {
    if (g_is64) return (int)((const long long*)ei)[pos];
    return ((const int*)ei)[pos];
}

// ---------------- CSR build ----------------
__global__ void zero_kernel() {
    int i = blockIdx.x * blockDim.x + threadIdx.x;
    if (i < NN) { g_cnt[i] = 0; g_cursor[i] = 0; }
}

__global__ void deg_kernel(const void* __restrict__ ei) {
    int e = blockIdx.x * blockDim.x + threadIdx.x;
    if (e >= NE) return;
    int t = load_idx(ei, (long long)NE + e);
    if ((unsigned)t < NN) atomicAdd(&g_cnt[t], 1);
}

__global__ void scanA_kernel() {
    int tid = threadIdx.x, lane = tid & 31, warp = tid >> 5;
    int i = blockIdx.x * 1024 + tid;
    int v = (i < NN) ? g_cnt[i] : 0;
    int x = v;
#pragma unroll
    for (int off = 1; off < 32; off <<= 1) {
        int n = __shfl_up_sync(0xFFFFFFFFu, x, off);
        if (lane >= off) x += n;
    }
    __shared__ int ws[32];
    if (lane == 31) ws[warp] = x;
    __syncthreads();
    if (warp == 0) {
        int s = ws[lane];
#pragma unroll
        for (int off = 1; off < 32; off <<= 1) {
            int n = __shfl_up_sync(0xFFFFFFFFu, s, off);
            if (lane >= off) s += n;
        }
        ws[lane] = s;
    }
    __syncthreads();
    int base = warp ? ws[warp - 1] : 0;
    int incl = x + base;
    if (i < NN) {
        g_ptr[i] = incl - v;
        g_invdeg[i] = 1.0f / fmaxf((float)v, 1.0f);
    }
    if (tid == 1023) g_bsum[blockIdx.x] = incl;
}

__global__ void scanB_kernel() {
    int tid = threadIdx.x, lane = tid & 31, warp = tid >> 5;
    int v = (tid < NB) ? g_bsum[tid] : 0;
    int x = v;
#pragma unroll
    for (int off = 1; off < 32; off <<= 1) {
        int n = __shfl_up_sync(0xFFFFFFFFu, x, off);
        if (lane >= off) x += n;
    }
    __shared__ int ws[2];
    if (lane == 31) ws[warp] = x;
    __syncthreads();
    int base = warp ? ws[0] : 0;
    int incl = x + base;
    if (tid < NB) g_boff[tid] = incl - v;
    if (tid == NB - 1) g_ptr[NN] = incl;
}

__global__ void scanC_kernel() {
    int i = blockIdx.x * 1024 + threadIdx.x;
    if (i < NN) g_ptr[i] += g_boff[blockIdx.x];
}

__global__ void fill_kernel(const void* __restrict__ ei) {
    int e = blockIdx.x * blockDim.x + threadIdx.x;
    if (e >= NE) return;
    int t = load_idx(ei, (long long)NE + e);
    int s = load_idx(ei, e);
    if ((unsigned)t >= NN || (unsigned)s >= NN) return;
    int pos = g_ptr[t] + atomicAdd(&g_cursor[t], 1);
    if ((unsigned)pos < NE) g_csr_src[pos] = s;
}

// ---------------- layer-1 aggregation: mean(x) -> left half of A1 ----------------
__global__ void agg1_kernel(const float* __restrict__ x) {
    int gid  = (blockIdx.x * blockDim.x + threadIdx.x) / 16;
    int lane = threadIdx.x % 16;
    if (gid >= NN) return;
    int beg = g_ptr[gid];
    int cnt = g_cnt[gid];
    float4 acc = make_float4(0.f, 0.f, 0.f, 0.f);
    for (int e = 0; e < cnt; e++) {
        int s = __ldg(&g_csr_src[beg + e]);
        float4 v = __ldg((const float4*)(x + (size_t)s * 64) + lane);
        acc.x += v.x; acc.y += v.y; acc.z += v.z; acc.w += v.w;
    }
    float inv = g_invdeg[gid];
    acc.x *= inv; acc.y *= inv; acc.z *= inv; acc.w *= inv;
    *((float4*)(g_A1 + (size_t)gid * 128) + lane) = acc;
}

// ---------------- fused agg + epilogue for layers 2/3 ----------------
template <int HSEL>
__global__ void agg_ew_kernel(const float* __restrict__ bias) {
    float* h = (HSEL == 0) ? g_h2 : g_h3;
    int gid  = (blockIdx.x * blockDim.x + threadIdx.x) / 32;
    int lane = threadIdx.x % 32;
    if (gid >= NN) return;
    int beg = g_ptr[gid];
    int cnt = g_cnt[gid];
    float4 acc = make_float4(0.f, 0.f, 0.f, 0.f);
    for (int e = 0; e < cnt; e++) {
        int s = __ldg(&g_csr_src[beg + e]);
        float4 v = __ldg((const float4*)(g_pre + (size_t)s * 256) + lane);
        acc.x += v.x; acc.y += v.y; acc.z += v.z; acc.w += v.w;
    }
    float inv = g_invdeg[gid];
    float4 pv = __ldg((const float4*)g_pre + (size_t)gid * 64 + 32 + lane);
    float4 bv = __ldg((const float4*)bias + lane);
    float4 r;
    r.x = fmaxf(acc.x * inv + pv.x + bv.x, 0.f);
    r.y = fmaxf(acc.y * inv + pv.y + bv.y, 0.f);
    r.z = fmaxf(acc.z * inv + pv.z + bv.z, 0.f);
    r.w = fmaxf(acc.w * inv + pv.w + bv.w, 0.f);
    ((float4*)h)[(size_t)gid * 32 + lane] = r;
}

__global__ void pack_x_kernel(const float4* __restrict__ x4) {
    int idx = blockIdx.x * blockDim.x + threadIdx.x;
    if (idx >= NN * 16) return;
    int i = idx >> 4, j = idx & 15;
    ((float4*)g_A1)[i * 32 + 16 + j] = x4[idx];
}

// ---------------- B prep: fp32 weights -> row-major [K][256] bf16 hi/lo ----------------
// L0: B[k][n] = k<64 ? Wf_l[k*256+n] : Wf_r[(k-64)*256+n]          (K=128)
// L1: B[k][n] = n<128 ? W0_l[k*128+n] : W0_r[k*128+n-128]          (K=256)
// L2: same as L1 with W1                                           (K=128)
template <int LAYER>
__global__ void bprep_kernel(const float* __restrict__ wl, const float* __restrict__ wr) {
    constexpr int K = (LAYER == 1) ? 256 : 128;
    constexpr size_t OFF = (LAYER == 0) ? 0 : (LAYER == 1) ? 32768 : 98304;
    int t = blockIdx.x * blockDim.x + threadIdx.x;
    if (t >= K * 256) return;
    int k = t >> 8;
    int n = t & 255;
    float w;
    if (LAYER == 0) w = (k < 64) ? wl[k * 256 + n] : wr[(k - 64) * 256 + n];
    else            w = (n < 128) ? wl[k * 128 + n] : wr[k * 128 + n - 128];
    unsigned short hs, ls;
    split_bf16(w, hs, ls);
    g_Bh[OFF + t] = *(__nv_bfloat16*)&hs;
    g_Bl[OFF + t] = *(__nv_bfloat16*)&ls;
}

// ---------------- mma.sync GEMM: C[M,256] = A[M,K] @ B[K,256], bf16 3-term split ----------------
// LAYER 0: A=g_A1 (K=128), +bias+relu -> g_h1
// LAYER 1: A=g_h1 (K=256)             -> g_pre
// LAYER 2: A=g_h2 (K=128)             -> g_pre
template <int LAYER>
__global__ __launch_bounds__(256, 2)
void mma_gemm_kernel(const float* __restrict__ bias) {
    constexpr int K = (LAYER == 1) ? 256 : 128;
    constexpr size_t BOFF = (LAYER == 0) ? 0 : (LAYER == 1) ? 32768 : 98304;
    const float* A = (LAYER == 0) ? g_A1 : (LAYER == 1) ? g_h1 : g_h2;
    float* C = (LAYER == 0) ? g_h1 : g_pre;

    __shared__ __align__(16) __nv_bfloat16 Ah[128][40];
    __shared__ __align__(16) __nv_bfloat16 Al[128][40];
    __shared__ __align__(16) __nv_bfloat16 Bh[32][136];
    __shared__ __align__(16) __nv_bfloat16 Bl[32][136];

    int tid = threadIdx.x, lane = tid & 31, wid = tid >> 5;
    int brow = blockIdx.x * 128;
    int bcol = blockIdx.y * 128;
    int wm = wid & 3;          // 0..3 -> warp rows wm*32
    int wn = wid >> 2;         // 0..1 -> warp cols wn*64

    uint32_t ah_base = smem_u32(Ah);
    uint32_t al_base = smem_u32(Al);
    uint32_t bh_base = smem_u32(Bh);
    uint32_t bl_base = smem_u32(Bl);

    float acc[2][8][4];
#pragma unroll
    for (int i = 0; i < 2; i++)
#pragma unroll
        for (int j = 0; j < 8; j++)
#pragma unroll
            for (int v = 0; v < 4; v++) acc[i][j][v] = 0.f;

    // ldmatrix lane addressing (constant over the k-loop)
    int lrow = lane & 15;             // row within 16
    int lcol = (lane >> 4) * 8;       // 0 or 8

    for (int kc = 0; kc < K / 32; kc++) {
        int k0 = kc * 32;
        // --- stage A (128 x 32 fp32 -> bf16 hi/lo) ---
#pragma unroll
        for (int it = 0; it < 4; it++) {
            int i = tid + it * 256;       // 0..1023 float4 slots
            int r = i >> 3;
            int c4 = (i & 7) * 4;
            int gr = brow + r;
            float4 v = make_float4(0.f, 0.f, 0.f, 0.f);
            if (gr < NN) v = *(const float4*)(A + (size_t)gr * K + k0 + c4);
            unsigned short hs[4], ls[4];
            split_bf16(v.x, hs[0], ls[0]);
            split_bf16(v.y, hs[1], ls[1]);
            split_bf16(v.z, hs[2], ls[2]);
            split_bf16(v.w, hs[3], ls[3]);
            *(uint2*)&Ah[r][c4] = make_uint2(hs[0] | (hs[1] << 16), hs[2] | (hs[3] << 16));
            *(uint2*)&Al[r][c4] = make_uint2(ls[0] | (ls[1] << 16), ls[2] | (ls[3] << 16));
        }
        // --- stage B (32 x 128 bf16 hi/lo, plain copy) ---
#pragma unroll
        for (int it = 0; it < 2; it++) {
            int i = tid + it * 256;       // 0..511 uint4 slots
            int r = i >> 4;
            int c8 = (i & 15) * 8;
            size_t go = BOFF + (size_t)(k0 + r) * 256 + bcol + c8;
            *(uint4*)&Bh[r][c8] = *(const uint4*)&g_Bh[go];
            *(uint4*)&Bl[r][c8] = *(const uint4*)&g_Bl[go];
        }
        __syncthreads();

        // --- compute: 2 k16 steps ---
#pragma unroll
        for (int ks = 0; ks < 2; ks++) {
            uint32_t ahf[2][4], alf[2][4];
#pragma unroll
            for (int mt = 0; mt < 2; mt++) {
                int ar = wm * 32 + mt * 16 + lrow;
                int ac = ks * 16 + lcol;
                uint32_t off = (uint32_t)(ar * 40 + ac) * 2;
                ldmatrix_x4(ahf[mt][0], ahf[mt][1], ahf[mt][2], ahf[mt][3], ah_base + off);
                ldmatrix_x4(alf[mt][0], alf[mt][1], alf[mt][2], alf[mt][3], al_base + off);
            }
#pragma unroll
            for (int np = 0; np < 4; np++) {
                int br = ks * 16 + lrow;
                int bc = wn * 64 + np * 16 + lcol;
                uint32_t off = (uint32_t)(br * 136 + bc) * 2;
                uint32_t bh0, bh1, bh2, bh3, bl0, bl1, bl2, bl3;
                ldmatrix_x4_trans(bh0, bh1, bh2, bh3, bh_base + off);
                ldmatrix_x4_trans(bl0, bl1, bl2, bl3, bl_base + off);
#pragma unroll
                for (int mt = 0; mt < 2; mt++) {
                    mma_bf16(acc[mt][np * 2 + 0], ahf[mt], bh0, bh1);
                    mma_bf16(acc[mt][np * 2 + 0], ahf[mt], bl0, bl1);
                    mma_bf16(acc[mt][np * 2 + 0], alf[mt], bh0, bh1);
                    mma_bf16(acc[mt][np * 2 + 1], ahf[mt], bh2, bh3);
                    mma_bf16(acc[mt][np * 2 + 1], ahf[mt], bl2, bl3);
                    mma_bf16(acc[mt][np * 2 + 1], alf[mt], bh2, bh3);
                }
            }
        }
        __syncthreads();
    }

    // --- epilogue ---
    int qrow = lane >> 2;        // 0..7
    int qcol = (lane & 3) * 2;   // 0,2,4,6
#pragma unroll
    for (int mt = 0; mt < 2; mt++) {
#pragma unroll
        for (int nf = 0; nf < 8; nf++) {
            int c = bcol + wn * 64 + nf * 8 + qcol;
#pragma unroll
            for (int half = 0; half < 2; half++) {
                int r = brow + wm * 32 + mt * 16 + qrow + half * 8;
                if (r >= NN) continue;
                float2 v = make_float2(acc[mt][nf][half * 2], acc[mt][nf][half * 2 + 1]);
                if (LAYER == 0) {
                    v.x = fmaxf(v.x + __ldg(bias + c), 0.f);
                    v.y = fmaxf(v.y + __ldg(bias + c + 1), 0.f);
                }
                *(float2*)(C + (size_t)r * 256 + c) = v;
            }
        }
    }
}

// ---------------- head: fold two linears into one ----------------
__global__ void combine_head_kernel(const float* __restrict__ Wlin, const float* __restrict__ blin,
                                    const float* __restrict__ Wlin2, const float* __restrict__ blin2) {
    int i = threadIdx.x;   // 128 threads
    float acc[8];
#pragma unroll
    for (int j = 0; j < 8; j++) acc[j] = 0.f;
    for (int k = 0; k < 128; k++) {
        float a = Wlin[i * 128 + k];
#pragma unroll
        for (int j = 0; j < 8; j++) acc[j] += a * Wlin2[k * 8 + j];
    }
#pragma unroll
    for (int j = 0; j < 8; j++) g_Wc[i * 8 + j] = acc[j];
    if (i < 8) {
        float s = blin2[i];
        for (int k = 0; k < 128; k++) s += blin[k] * Wlin2[k * 8 + i];
        g_bc[i] = s;
    }
}

__global__ void head_kernel(float* __restrict__ out) {
    __shared__ float sW[8][128];
    __shared__ float sb[8];
    int tid = threadIdx.x;
    for (int i = tid; i < 1024; i += blockDim.x) {
        int k = i >> 3, j = i & 7;
        sW[j][k] = g_Wc[k * 8 + j];
    }
    if (tid < 8) sb[tid] = g_bc[tid];
    __syncthreads();
    int warp = tid / 32, lane = tid % 32;
    int row = blockIdx.x * 8 + warp;
    if (row >= NN) return;
    float4 a = *(const float4*)(g_h3 + (size_t)row * 128 + lane * 4);
    float acc[8];
#pragma unroll
    for (int j = 0; j < 8; j++) {
        float4 w = *(const float4*)&sW[j][lane * 4];
        acc[j] = a.x * w.x + a.y * w.y + a.z * w.z + a.w * w.w;
    }
#pragma unroll
    for (int j = 0; j < 8; j++) {
        float v = acc[j];
#pragma unroll
        for (int off = 16; off; off >>= 1) v += __shfl_down_sync(0xFFFFFFFFu, v, off);
        if (lane == 0) out[row * 8 + j] = v + sb[j];
    }
}

// ---------------- launch ----------------
extern "C" void kernel_launch(void* const* d_in, const int* in_sizes, int n_in,
                              void* d_out, int out_size) {
    const float* x      = (const float*)d_in[0];
    const void*  ei     = d_in[1];
    const float* Wf_l   = (const float*)d_in[2];
    const float* bf     = (const float*)d_in[3];
    const float* Wf_r   = (const float*)d_in[4];
    const float* W0_l   = (const float*)d_in[5];
    const float* b0     = (const float*)d_in[6];
    const float* W0_r   = (const float*)d_in[7];
    const float* W1_l   = (const float*)d_in[8];
    const float* b1     = (const float*)d_in[9];
    const float* W1_r   = (const float*)d_in[10];
    const float* W_lin  = (const float*)d_in[11];
    const float* b_lin  = (const float*)d_in[12];
    const float* W_lin2 = (const float*)d_in[13];
    const float* b_lin2 = (const float*)d_in[14];
    float* out = (float*)d_out;

    const int TB = 256;
    const dim3 GG((NN + 127) / 128, 2);

    // ---- dtype probe + CSR build ----
    detect_kernel<<<1, 256>>>((const unsigned int*)ei);
    zero_kernel<<<(NN + TB - 1) / TB, TB>>>();
    deg_kernel<<<(NE + TB - 1) / TB, TB>>>(ei);
    scanA_kernel<<<NB, 1024>>>();
    scanB_kernel<<<1, 64>>>();
    scanC_kernel<<<NB, 1024>>>();
    fill_kernel<<<(NE + TB - 1) / TB, TB>>>(ei);

    // ---- weight prep ----
    bprep_kernel<0><<<(128 * 256 + TB - 1) / TB, TB>>>(Wf_l, Wf_r);
    bprep_kernel<1><<<(256 * 256 + TB - 1) / TB, TB>>>(W0_l, W0_r);
    bprep_kernel<2><<<(128 * 256 + TB - 1) / TB, TB>>>(W1_l, W1_r);
    combine_head_kernel<<<1, 128>>>(W_lin, b_lin, W_lin2, b_lin2);
    pack_x_kernel<<<(NN * 16 + TB - 1) / TB, TB>>>((const float4*)x);

    // ---- layer 1 ----
    agg1_kernel<<<(NN * 16 + TB - 1) / TB, TB>>>(x);
    mma_gemm_kernel<0><<<GG, 256>>>(bf);
    // ---- layer 2 ----
    mma_gemm_kernel<1><<<GG, 256>>>(nullptr);
    agg_ew_kernel<0><<<(NN * 32 + TB - 1) / TB, TB>>>(b0);
    // ---- layer 3 ----
    mma_gemm_kernel<2><<<GG, 256>>>(nullptr);
    agg_ew_kernel<1><<<(NN * 32 + TB - 1) / TB, TB>>>(b1);

    // ---- folded head ----
    head_kernel<<<(NN + 7) / 8, 256>>>(out);
    (void)in_sizes; (void)n_in; (void)out_size;
}